// round 1
// baseline (speedup 1.0000x reference)
#include <cuda_runtime.h>

// ---------------------------------------------------------------------------
// LNon_16621523436082: histogram-equalization-ish pointwise transform.
//   d = data * ct (scalar); 5-bin histogram over [min(d)-0.1, max(d)+0.1];
//   accum = cumsum(prob)*5; index = interp(grid->accum, d);
//   frame = interp(accum->grid, 0..4); theta/velo = gather-interp of
//   (frame + 0.001*param); out = (d*(1+velo*sin(theta)) + velo*cos(theta))*st
//
// 3 full passes over the 128 MiB input (minmax -> hist -> elementwise),
// tiny single-block kernels in between. Histogram counts emulate the
// reference's fp32 +1.0 scatter-add saturation at 2^24.
// ---------------------------------------------------------------------------

#define NBLK 2048
#define TPB  256
#define SATF 16777216.0f

__device__ float        g_bmin[NBLK];
__device__ float        g_bmax[NBLK];
__device__ unsigned int g_bhist[NBLK * 5];
__device__ float        g_dmin, g_width, g_invw;
__device__ float        g_grid[5], g_accum[5], g_slope[4], g_tA[5], g_tV[5];

// ---- pass 1: per-block min/max of raw data -------------------------------
__global__ void k_minmax(const float4* __restrict__ d4, int n4, int n) {
    float mn = 3.4028235e38f, mx = -3.4028235e38f;
    int stride = gridDim.x * blockDim.x;
    int gtid = blockIdx.x * blockDim.x + threadIdx.x;
    for (int i = gtid; i < n4; i += stride) {
        float4 v = d4[i];
        mn = fminf(mn, fminf(fminf(v.x, v.y), fminf(v.z, v.w)));
        mx = fmaxf(mx, fmaxf(fmaxf(v.x, v.y), fmaxf(v.z, v.w)));
    }
    int base = n4 * 4;
    if (gtid < n - base) {
        float v = ((const float*)d4)[base + gtid];
        mn = fminf(mn, v); mx = fmaxf(mx, v);
    }
    #pragma unroll
    for (int o = 16; o; o >>= 1) {
        mn = fminf(mn, __shfl_xor_sync(0xffffffffu, mn, o));
        mx = fmaxf(mx, __shfl_xor_sync(0xffffffffu, mx, o));
    }
    __shared__ float smn[8], smx[8];
    int w = threadIdx.x >> 5;
    if ((threadIdx.x & 31) == 0) { smn[w] = mn; smx[w] = mx; }
    __syncthreads();
    if (threadIdx.x < 8) {
        mn = smn[threadIdx.x]; mx = smx[threadIdx.x];
        #pragma unroll
        for (int o = 4; o; o >>= 1) {
            mn = fminf(mn, __shfl_xor_sync(0xffu, mn, o));
            mx = fmaxf(mx, __shfl_xor_sync(0xffu, mx, o));
        }
        if (threadIdx.x == 0) { g_bmin[blockIdx.x] = mn; g_bmax[blockIdx.x] = mx; }
    }
}

// ---- reduce blocks, derive dmin/width ------------------------------------
__global__ void k_prep(const float* __restrict__ ctp) {
    int t = threadIdx.x;  // 1024 threads, NBLK=2048
    float mn = fminf(g_bmin[t], g_bmin[t + 1024]);
    float mx = fmaxf(g_bmax[t], g_bmax[t + 1024]);
    #pragma unroll
    for (int o = 16; o; o >>= 1) {
        mn = fminf(mn, __shfl_xor_sync(0xffffffffu, mn, o));
        mx = fmaxf(mx, __shfl_xor_sync(0xffffffffu, mx, o));
    }
    __shared__ float smn[32], smx[32];
    int w = t >> 5;
    if ((t & 31) == 0) { smn[w] = mn; smx[w] = mx; }
    __syncthreads();
    if (t < 32) {
        mn = smn[t]; mx = smx[t];
        #pragma unroll
        for (int o = 16; o; o >>= 1) {
            mn = fminf(mn, __shfl_xor_sync(0xffffffffu, mn, o));
            mx = fmaxf(mx, __shfl_xor_sync(0xffffffffu, mx, o));
        }
        if (t == 0) {
            float ct = *ctp;
            float a = ct * mn, b = ct * mx;
            float lo = fminf(a, b), hi = fmaxf(a, b);
            float dmin = lo - 0.1f;
            float dmax = hi + 0.1f;
            float width = (dmax - dmin) / 5.0f;
            g_dmin = dmin; g_width = width; g_invw = 1.0f / width;
        }
    }
}

// ---- pass 2: 5-bin histogram (exact integer counts) ----------------------
__global__ void k_hist(const float4* __restrict__ d4, const float* __restrict__ ctp,
                       int n4, int n) {
    float ct = __ldg(ctp);
    float dmin = g_dmin, invw = g_invw;
    unsigned c0 = 0, c1 = 0, c2 = 0, c3 = 0, c4 = 0;
    int stride = gridDim.x * blockDim.x;
    int gtid = blockIdx.x * blockDim.x + threadIdx.x;
    for (int i = gtid; i < n4; i += stride) {
        float4 v = d4[i];
        #pragma unroll
        for (int j = 0; j < 4; j++) {
            float x = ((j == 0) ? v.x : (j == 1) ? v.y : (j == 2) ? v.z : v.w) * ct;
            int b = (int)floorf((x - dmin) * invw);
            b = min(max(b, 0), 4);
            c0 += (b == 0); c1 += (b == 1); c2 += (b == 2); c3 += (b == 3); c4 += (b == 4);
        }
    }
    int base = n4 * 4;
    if (gtid < n - base) {
        float x = ((const float*)d4)[base + gtid] * ct;
        int b = (int)floorf((x - dmin) * invw);
        b = min(max(b, 0), 4);
        c0 += (b == 0); c1 += (b == 1); c2 += (b == 2); c3 += (b == 3); c4 += (b == 4);
    }
    __shared__ unsigned s[5];
    if (threadIdx.x < 5) s[threadIdx.x] = 0;
    __syncthreads();
    atomicAdd(&s[0], c0); atomicAdd(&s[1], c1); atomicAdd(&s[2], c2);
    atomicAdd(&s[3], c3); atomicAdd(&s[4], c4);
    __syncthreads();
    if (threadIdx.x < 5) g_bhist[blockIdx.x * 5 + threadIdx.x] = s[threadIdx.x];
}

// ---- reduce histogram, compute accum/grid/slope/frame/tA/tV --------------
__global__ void k_stats(const float* __restrict__ params) {
    __shared__ unsigned tot[5];
    if (threadIdx.x < 5) tot[threadIdx.x] = 0;
    __syncthreads();
    unsigned c[5] = {0, 0, 0, 0, 0};
    for (int b = threadIdx.x; b < NBLK; b += blockDim.x)
        #pragma unroll
        for (int j = 0; j < 5; j++) c[j] += g_bhist[b * 5 + j];
    #pragma unroll
    for (int j = 0; j < 5; j++) atomicAdd(&tot[j], c[j]);
    __syncthreads();
    if (threadIdx.x == 0) {
        // emulate the reference's fp32 +1.0 scatter-add: saturates at 2^24
        float counts[5];
        #pragma unroll
        for (int j = 0; j < 5; j++) counts[j] = fminf((float)tot[j], SATF);
        float sum = counts[0] + counts[1] + counts[2] + counts[3] + counts[4];
        float accum[5];
        float a = 0.0f;
        #pragma unroll
        for (int j = 0; j < 5; j++) { a += counts[j] / sum; accum[j] = a * 5.0f; }
        float dmin = g_dmin, width = g_width;
        float edges[6];
        #pragma unroll
        for (int i = 0; i < 6; i++) edges[i] = dmin + width * (float)i;
        float grid[5];
        #pragma unroll
        for (int i = 0; i < 5; i++) grid[i] = 0.5f * (edges[i + 1] + edges[i]);
        float slope[4];
        #pragma unroll
        for (int j = 0; j < 4; j++) {
            float den = grid[j + 1] - grid[j];
            if (den == 0.0f) den = 1.0f;
            slope[j] = (accum[j + 1] - accum[j]) / den;
        }
        float frame[5];
        #pragma unroll
        for (int i = 0; i < 5; i++) {
            float xq = (float)i;
            int pos = 0;
            #pragma unroll
            for (int k = 0; k < 5; k++) pos += (accum[k] < xq);
            int idx = min(max(pos - 1, 0), 3);
            float den = accum[idx + 1] - accum[idx];
            if (den == 0.0f) den = 1.0f;
            frame[i] = grid[idx] + (grid[idx + 1] - grid[idx]) / den * (xq - accum[idx]);
        }
        #pragma unroll
        for (int i = 0; i < 5; i++) {
            g_grid[i]  = grid[i];
            g_accum[i] = accum[i];
            g_tA[i]    = frame[i] + 0.001f * params[i];       // theta row
            g_tV[i]    = frame[i] + 0.001f * params[5 + i];   // velocity row
        }
        #pragma unroll
        for (int j = 0; j < 4; j++) g_slope[j] = slope[j];
    }
}

// ---- pass 3: elementwise transform ---------------------------------------
__global__ void k_main(const float4* __restrict__ d4, const float* __restrict__ ctp,
                       const float* __restrict__ stp, float4* __restrict__ out,
                       int n4, int n) {
    __shared__ float sg[5], sa[5], ssl[4], sA[5], sV[5];
    if (threadIdx.x < 5) {
        sg[threadIdx.x] = g_grid[threadIdx.x];
        sa[threadIdx.x] = g_accum[threadIdx.x];
        sA[threadIdx.x] = g_tA[threadIdx.x];
        sV[threadIdx.x] = g_tV[threadIdx.x];
        if (threadIdx.x < 4) ssl[threadIdx.x] = g_slope[threadIdx.x];
    }
    __syncthreads();
    float ct = __ldg(ctp), st = __ldg(stp);

    auto f = [&](float x) -> float {
        float v = x * ct;
        int pos = (v > sg[0]) + (v > sg[1]) + (v > sg[2]) + (v > sg[3]) + (v > sg[4]);
        int idx = min(max(pos - 1, 0), 3);
        float index = sa[idx] + ssl[idx] * (v - sg[idx]);
        float bf = floorf(index);
        float p = index - bf;
        int bi = (int)bf;
        int b = min(max(bi, 0), 4);
        int e = min(max(bi + 1, 0), 4);
        float th = (1.0f - p) * sA[b] + p * sA[e];
        float vl = (1.0f - p) * sV[b] + p * sV[e];
        float s, co;
        __sincosf(th, &s, &co);
        return (v * (1.0f + vl * s) + vl * co) * st;
    };

    int stride = gridDim.x * blockDim.x;
    int gtid = blockIdx.x * blockDim.x + threadIdx.x;
    for (int i = gtid; i < n4; i += stride) {
        float4 v = d4[i];
        float4 o;
        o.x = f(v.x); o.y = f(v.y); o.z = f(v.z); o.w = f(v.w);
        out[i] = o;
    }
    int base = n4 * 4;
    if (gtid < n - base) {
        ((float*)out)[base + gtid] = f(((const float*)d4)[base + gtid]);
    }
}

extern "C" void kernel_launch(void* const* d_in, const int* in_sizes, int n_in,
                              void* d_out, int out_size) {
    const float* data   = (const float*)d_in[0];
    const float* params = (const float*)d_in[1];
    const float* ctp    = (const float*)d_in[2];
    const float* stp    = (const float*)d_in[3];
    float* out = (float*)d_out;
    int n  = in_sizes[0];
    int n4 = n / 4;

    k_minmax<<<NBLK, TPB>>>((const float4*)data, n4, n);
    k_prep<<<1, 1024>>>(ctp);
    k_hist<<<NBLK, TPB>>>((const float4*)data, ctp, n4, n);
    k_stats<<<1, 256>>>(params);
    k_main<<<NBLK, TPB>>>((const float4*)data, ctp, stp, (float4*)out, n4, n);
}

// round 4
// speedup vs baseline: 1.0206x; 1.0206x over previous
#include <cuda_runtime.h>

// ---------------------------------------------------------------------------
// LNon_16621523436082 — 3 full passes + 2 tiny kernels, L2-reuse scheduled:
//   k_minmax  (fwd):  per-block min/max of raw data        [DRAM read]
//   k_prep    (1 blk): reduce -> dmin/width; zero g_hist
//   k_hist    (bwd):  5-bin histogram, backward traversal  [mostly L2]
//   k_stats   (1 blk): counts (fp32-saturation emulated) -> accum/frame/tables
//   k_main    (fwd):  elementwise transform, __stcs stores [L2 reads + DRAM wr]
// L1 is flushed per launch; L2 (~120MB) persists across graph nodes, so
// alternating traversal direction turns passes 2-3 into mostly-L2 traffic.
// ---------------------------------------------------------------------------

#define NBLK 2048
#define TPB  256
#define SATF 16777216.0f
#define FLTMAX 3.4028235e38f

__device__ float    g_bmin[NBLK];
__device__ float    g_bmax[NBLK];
__device__ unsigned g_hist[8];
__device__ float    g_dmin, g_width, g_invw;
__device__ float    g_sg[5], g_sa[5], g_ssl[4], g_sA[5], g_sV[5];

// ---- pass 1: per-block min/max of raw data (forward) ---------------------
__global__ void __launch_bounds__(TPB) k_minmax(const float4* __restrict__ d4, int n4, int n) {
    float mn = FLTMAX, mx = -FLTMAX;
    int stride = gridDim.x * blockDim.x;
    int gtid = blockIdx.x * blockDim.x + threadIdx.x;
    for (int i = gtid; i < n4; i += stride) {
        float4 v = d4[i];
        mn = fminf(mn, fminf(fminf(v.x, v.y), fminf(v.z, v.w)));
        mx = fmaxf(mx, fmaxf(fmaxf(v.x, v.y), fmaxf(v.z, v.w)));
    }
    int base = n4 * 4;
    if (gtid < n - base) {
        float v = ((const float*)d4)[base + gtid];
        mn = fminf(mn, v); mx = fmaxf(mx, v);
    }
    #pragma unroll
    for (int o = 16; o; o >>= 1) {
        mn = fminf(mn, __shfl_xor_sync(0xffffffffu, mn, o));
        mx = fmaxf(mx, __shfl_xor_sync(0xffffffffu, mx, o));
    }
    __shared__ float smn[8], smx[8];
    int w = threadIdx.x >> 5;
    if ((threadIdx.x & 31) == 0) { smn[w] = mn; smx[w] = mx; }
    __syncthreads();
    if (threadIdx.x < 8) {
        mn = smn[threadIdx.x]; mx = smx[threadIdx.x];
        #pragma unroll
        for (int o = 4; o; o >>= 1) {
            mn = fminf(mn, __shfl_xor_sync(0xffu, mn, o));
            mx = fmaxf(mx, __shfl_xor_sync(0xffu, mx, o));
        }
        if (threadIdx.x == 0) { g_bmin[blockIdx.x] = mn; g_bmax[blockIdx.x] = mx; }
    }
}

// ---- reduce blocks, derive dmin/width, zero histogram --------------------
__global__ void k_prep(const float* __restrict__ ctp) {
    int t = threadIdx.x;  // 1024 threads; NBLK == 2 * 1024
    float mn = fminf(g_bmin[t], g_bmin[t + 1024]);
    float mx = fmaxf(g_bmax[t], g_bmax[t + 1024]);
    #pragma unroll
    for (int o = 16; o; o >>= 1) {
        mn = fminf(mn, __shfl_xor_sync(0xffffffffu, mn, o));
        mx = fmaxf(mx, __shfl_xor_sync(0xffffffffu, mx, o));
    }
    __shared__ float smn[32], smx[32];
    int w = t >> 5;
    if ((t & 31) == 0) { smn[w] = mn; smx[w] = mx; }
    __syncthreads();
    if (t < 32) {
        mn = smn[t]; mx = smx[t];
        #pragma unroll
        for (int o = 16; o; o >>= 1) {
            mn = fminf(mn, __shfl_xor_sync(0xffffffffu, mn, o));
            mx = fmaxf(mx, __shfl_xor_sync(0xffffffffu, mx, o));
        }
        if (t == 0) {
            float ct = *ctp;
            float a = ct * mn, b = ct * mx;
            float lo = fminf(a, b), hi = fmaxf(a, b);
            float dmin = lo - 0.1f;
            float dmax = hi + 0.1f;
            float width = (dmax - dmin) / 5.0f;
            g_dmin = dmin; g_width = width; g_invw = 1.0f / width;
            #pragma unroll
            for (int k = 0; k < 5; k++) g_hist[k] = 0u;
        }
    }
}

// ---- pass 2: 5-bin histogram, BACKWARD traversal (L2 reuse) --------------
__global__ void __launch_bounds__(TPB) k_hist(const float4* __restrict__ d4, const float* __restrict__ ctp,
                                              int n4, int n) {
    float ct = __ldg(ctp);
    float dmin = g_dmin, invw = g_invw;
    unsigned c0 = 0, c1 = 0, c2 = 0, c3 = 0, c4 = 0;
    int stride = gridDim.x * blockDim.x;
    int gtid = blockIdx.x * blockDim.x + threadIdx.x;
    for (int i = n4 - 1 - gtid; i >= 0; i -= stride) {
        float4 v = d4[i];
        #pragma unroll
        for (int j = 0; j < 4; j++) {
            float x = ((j == 0) ? v.x : (j == 1) ? v.y : (j == 2) ? v.z : v.w) * ct;
            int b = (int)floorf((x - dmin) * invw);
            b = min(max(b, 0), 4);
            c0 += (b == 0); c1 += (b == 1); c2 += (b == 2); c3 += (b == 3); c4 += (b == 4);
        }
    }
    int base = n4 * 4;
    if (gtid < n - base) {
        float x = ((const float*)d4)[base + gtid] * ct;
        int b = (int)floorf((x - dmin) * invw);
        b = min(max(b, 0), 4);
        c0 += (b == 0); c1 += (b == 1); c2 += (b == 2); c3 += (b == 3); c4 += (b == 4);
    }
    __shared__ unsigned s[5];
    if (threadIdx.x < 5) s[threadIdx.x] = 0;
    __syncthreads();
    atomicAdd(&s[0], c0); atomicAdd(&s[1], c1); atomicAdd(&s[2], c2);
    atomicAdd(&s[3], c3); atomicAdd(&s[4], c4);
    __syncthreads();
    if (threadIdx.x < 5) atomicAdd(&g_hist[threadIdx.x], s[threadIdx.x]);
}

// ---- stats: counts -> accum/grid/slope/frame/tA/tV (5 words in) ----------
__global__ void k_stats(const float* __restrict__ params) {
    if (threadIdx.x == 0) {
        // emulate the reference's fp32 +1.0 scatter-add: saturates at 2^24
        float counts[5];
        #pragma unroll
        for (int j = 0; j < 5; j++) counts[j] = fminf((float)g_hist[j], SATF);
        float sum = counts[0] + counts[1] + counts[2] + counts[3] + counts[4];
        float accum[5];
        float a = 0.0f;
        #pragma unroll
        for (int j = 0; j < 5; j++) { a += counts[j] / sum; accum[j] = a * 5.0f; }
        float dmin = g_dmin, width = g_width;
        float grid[5];
        #pragma unroll
        for (int i = 0; i < 5; i++) {
            float e0 = dmin + width * (float)i;
            float e1 = dmin + width * (float)(i + 1);
            grid[i] = 0.5f * (e0 + e1);
        }
        #pragma unroll
        for (int j = 0; j < 4; j++) {
            float den = grid[j + 1] - grid[j];
            if (den == 0.0f) den = 1.0f;
            g_ssl[j] = (accum[j + 1] - accum[j]) / den;
        }
        float frame[5];
        #pragma unroll
        for (int i = 0; i < 5; i++) {
            float xq = (float)i;
            int pos = 0;
            #pragma unroll
            for (int k = 0; k < 5; k++) pos += (accum[k] < xq);
            int idx = min(max(pos - 1, 0), 3);
            float den = accum[idx + 1] - accum[idx];
            if (den == 0.0f) den = 1.0f;
            frame[i] = grid[idx] + (grid[idx + 1] - grid[idx]) / den * (xq - accum[idx]);
        }
        #pragma unroll
        for (int i = 0; i < 5; i++) {
            g_sg[i] = grid[i];
            g_sa[i] = accum[i];
            g_sA[i] = frame[i] + 0.001f * params[i];       // theta row
            g_sV[i] = frame[i] + 0.001f * params[5 + i];   // velocity row
        }
    }
}

// ---- pass 3: elementwise transform, FORWARD, streaming stores ------------
__global__ void __launch_bounds__(TPB) k_main(const float4* __restrict__ d4, const float* __restrict__ ctp,
                                              const float* __restrict__ stp, float4* __restrict__ out,
                                              int n4, int n) {
    __shared__ float sg[5], sa[5], ssl[4], sA[5], sV[5];
    if (threadIdx.x < 5) {
        sg[threadIdx.x] = g_sg[threadIdx.x];
        sa[threadIdx.x] = g_sa[threadIdx.x];
        sA[threadIdx.x] = g_sA[threadIdx.x];
        sV[threadIdx.x] = g_sV[threadIdx.x];
        if (threadIdx.x < 4) ssl[threadIdx.x] = g_ssl[threadIdx.x];
    }
    __syncthreads();
    float ct = __ldg(ctp), st = __ldg(stp);

    auto f = [&](float x) -> float {
        float v = x * ct;
        int pos = (v > sg[0]) + (v > sg[1]) + (v > sg[2]) + (v > sg[3]) + (v > sg[4]);
        int idx = min(max(pos - 1, 0), 3);
        float index = sa[idx] + ssl[idx] * (v - sg[idx]);
        float bf = floorf(index);
        float p = index - bf;
        int bi = (int)bf;
        int b = min(max(bi, 0), 4);
        int e = min(max(bi + 1, 0), 4);
        float th = (1.0f - p) * sA[b] + p * sA[e];
        float vl = (1.0f - p) * sV[b] + p * sV[e];
        float s, co;
        __sincosf(th, &s, &co);
        return (v * (1.0f + vl * s) + vl * co) * st;
    };

    int stride = gridDim.x * blockDim.x;
    int gtid = blockIdx.x * blockDim.x + threadIdx.x;
    for (int i = gtid; i < n4; i += stride) {
        float4 v = d4[i];
        float4 o;
        o.x = f(v.x); o.y = f(v.y); o.z = f(v.z); o.w = f(v.w);
        __stcs(&out[i], o);            // streaming store: don't evict input
    }
    int base = n4 * 4;
    if (gtid < n - base) {
        float r = f(((const float*)d4)[base + gtid]);
        __stcs(&((float*)out)[base + gtid], r);
    }
}

extern "C" void kernel_launch(void* const* d_in, const int* in_sizes, int n_in,
                              void* d_out, int out_size) {
    const float* data   = (const float*)d_in[0];
    const float* params = (const float*)d_in[1];
    const float* ctp    = (const float*)d_in[2];
    const float* stp    = (const float*)d_in[3];
    float* out = (float*)d_out;
    int n  = in_sizes[0];
    int n4 = n / 4;

    k_minmax<<<NBLK, TPB>>>((const float4*)data, n4, n);
    k_prep<<<1, 1024>>>(ctp);
    k_hist<<<NBLK, TPB>>>((const float4*)data, ctp, n4, n);
    k_stats<<<1, 32>>>(params);
    k_main<<<NBLK, TPB>>>((const float4*)data, ctp, stp, (float4*)out, n4, n);
}